// round 14
// baseline (speedup 1.0000x reference)
#include <cuda_runtime.h>
#include <cuda_fp16.h>

#define B_ 2
#define L_ 24
#define C_ 16
#define H_ 64
#define W_ 64
#define HW_ 4096

// fp16 images, layout [b][l][cq(2)][HW][8ch] : 16 B per (pixel, channel-oct)
__device__ __half g_imgh[(size_t)B_ * L_ * 2 * HW_ * 8];

// ---------------------------------------------------------------------------
// Kernel 1: repack [B][L][C][HW] fp32 -> [b][l][cq][HW][8] fp16.
// ---------------------------------------------------------------------------
__global__ __launch_bounds__(256) void transpose_kernel(const float* __restrict__ images) {
    int idx = blockIdx.x * blockDim.x + threadIdx.x;   // over B*L*2*HW
    int p = idx & (HW_ - 1);
    int cq = (idx >> 12) & 1;
    int bl = idx >> 13;
    const float* src = images + ((size_t)bl * C_ + cq * 8) * HW_ + p;
    __half2 h[4];
#pragma unroll
    for (int j = 0; j < 4; ++j)
        h[j] = __floats2half2_rn(src[(2 * j) * HW_], src[(2 * j + 1) * HW_]);
    ((uint4*)g_imgh)[idx] = *(uint4*)h;
}

// ---------------------------------------------------------------------------
// Accumulate 8 fp16 channels (one uint4) * weight into fp32 acc.
// ---------------------------------------------------------------------------
__device__ __forceinline__ void accum8(float* acc, uint4 a, float w) {
    unsigned wds[4] = {a.x, a.y, a.z, a.w};
#pragma unroll
    for (int j = 0; j < 4; ++j) {
        float2 f = __half22float2(*(__half2*)&wds[j]);
        acc[2 * j]     = fmaf(w, f.x, acc[2 * j]);
        acc[2 * j + 1] = fmaf(w, f.y, acc[2 * j + 1]);
    }
}

struct Corners {
    int p00, p10, p01, p11;
    float w00, w10, w01, w11;
};

// Compute corner indices + weights for one pixel.
__device__ __forceinline__ Corners make_corners(float ax, float yf,
                                                float relx, float rely) {
    Corners c;
    // wrap x: u = (gx+1) mod 2, ix = u*32 - 0.5 in [-0.5, 63.5)
    float u0 = ax + relx;
    float u = u0 - 2.0f * floorf(0.5f * u0);
    float ixf = fmaf(u, 32.0f, -0.5f);
    float iyf = fmaf(rely, 32.0f, yf);

    float x0f = floorf(ixf), y0f = floorf(iyf);
    float wx1 = ixf - x0f, wy1 = iyf - y0f;
    float wx0 = 1.0f - wx1, wy0 = 1.0f - wy1;
    int x0 = (int)x0f, y0 = (int)y0f;

    if (x0 < 0) wx0 = 0.0f;
    if (x0 > 62) wx1 = 0.0f;
    if ((unsigned)y0 > 63u) wy0 = 0.0f;
    if ((unsigned)(y0 + 1) > 63u) wy1 = 0.0f;

    c.w00 = wx0 * wy0; c.w10 = wx1 * wy0;
    c.w01 = wx0 * wy1; c.w11 = wx1 * wy1;

    int x0c = max(x0, 0), x1c = min(x0 + 1, 63);
    int y0c = min(max(y0, 0), 63), y1c = min(max(y0 + 1, 0), 63);
    c.p00 = (y0c << 6) + x0c; c.p10 = (y0c << 6) + x1c;
    c.p01 = (y1c << 6) + x0c; c.p11 = (y1c << 6) + x1c;
    return c;
}

// ---------------------------------------------------------------------------
// Sample one frame for TWO pixels: all 16 corner loads issued before any
// accumulation (double MLP per warp-slot).
// ---------------------------------------------------------------------------
__device__ __forceinline__ void sample_frame2(const uint4* __restrict__ imgu,
                                              float axA, float axB, float yf,
                                              float rxA, float ryA,
                                              float rxB, float ryB,
                                              float* accA, float* accB) {
    Corners cA = make_corners(axA, yf, rxA, ryA);
    Corners cB = make_corners(axB, yf, rxB, ryB);
    const uint4* hi = imgu + HW_;

    // 16 batched loads
    uint4 a00 = imgu[cA.p00], a10 = imgu[cA.p10], a01 = imgu[cA.p01], a11 = imgu[cA.p11];
    uint4 A00 = hi[cA.p00],   A10 = hi[cA.p10],   A01 = hi[cA.p01],   A11 = hi[cA.p11];
    uint4 b00 = imgu[cB.p00], b10 = imgu[cB.p10], b01 = imgu[cB.p01], b11 = imgu[cB.p11];
    uint4 B00 = hi[cB.p00],   B10 = hi[cB.p10],   B01 = hi[cB.p01],   B11 = hi[cB.p11];

    accum8(accA,     a00, cA.w00); accum8(accA,     a10, cA.w10);
    accum8(accA,     a01, cA.w01); accum8(accA,     a11, cA.w11);
    accum8(accA + 8, A00, cA.w00); accum8(accA + 8, A10, cA.w10);
    accum8(accA + 8, A01, cA.w01); accum8(accA + 8, A11, cA.w11);

    accum8(accB,     b00, cB.w00); accum8(accB,     b10, cB.w10);
    accum8(accB,     b01, cB.w01); accum8(accB,     b11, cB.w11);
    accum8(accB + 8, B00, cB.w00); accum8(accB + 8, B10, cB.w10);
    accum8(accB + 8, B01, cB.w01); accum8(accB + 8, B11, cB.w11);
}

// ---------------------------------------------------------------------------
// Kernel 2: main gather, 2 pixels per thread (x and x+32 of one row).
// Block = 128 threads = 4 rows (warp = one row). Grid (16, 24, 2), t desc.
// ---------------------------------------------------------------------------
__global__ __launch_bounds__(128) void warp_kernel(const float* __restrict__ flows,
                                                   float* __restrict__ out) {
    int tid = threadIdx.x;
    int x = tid & 31;                       // lane -> pixel A = x, B = x+32
    int y = (blockIdx.x << 2) + (tid >> 5); // 4 rows per block
    int t = (L_ - 1) - (int)blockIdx.y;
    int b = blockIdx.z;
    int pA = (y << 6) + x;                  // pB = pA + 32

    float axA = (float)(2 * x + 1) * (1.0f / 64.0f);
    float axB = (float)(2 * (x + 32) + 1) * (1.0f / 64.0f);
    float yf = (float)y;

    const float* fptr = flows + ((size_t)(b * L_ + t) * 2) * HW_ + pA;
    const uint4* imgu = (const uint4*)g_imgh + (size_t)(b * L_ + t) * 2 * HW_;

    float rxA = 0.0f, ryA = 0.0f, rxB = 0.0f, ryB = 0.0f;
    float accA[C_], accB[C_];
#pragma unroll
    for (int c = 0; c < C_; ++c) { accA[c] = 0.0f; accB[c] = 0.0f; }

    for (int k = t; k > 0; --k) {
        float fxA = fptr[0],  fyA = fptr[HW_];
        float fxB = fptr[32], fyB = fptr[HW_ + 32];
        sample_frame2(imgu, axA, axB, yf, rxA, ryA, rxB, ryB, accA, accB);
        rxA += fxA; ryA += fyA;
        rxB += fxB; ryB += fyB;
        fptr -= 2 * HW_;
        imgu -= 2 * HW_;
    }
    // k = 0: no flow update
    sample_frame2(imgu, axA, axB, yf, rxA, ryA, rxB, ryB, accA, accB);

    // out layout [B][L][C][H][W]
    float* op = out + ((size_t)(b * L_ + t) * C_) * HW_ + pA;
#pragma unroll
    for (int c = 0; c < C_; ++c) {
        op[c * HW_]      = accA[c];
        op[c * HW_ + 32] = accB[c];
    }
}

extern "C" void kernel_launch(void* const* d_in, const int* in_sizes, int n_in,
                              void* d_out, int out_size) {
    const float* flows = (const float*)d_in[0];
    const float* images = (const float*)d_in[1];
    float* out = (float*)d_out;

    transpose_kernel<<<(B_ * L_ * 2 * HW_) / 256, 256>>>(images);
    dim3 grid(16, L_, B_);
    warp_kernel<<<grid, 128>>>(flows, out);
}

// round 15
// speedup vs baseline: 1.2953x; 1.2953x over previous
#include <cuda_runtime.h>
#include <cuda_fp16.h>

#define B_ 2
#define L_ 24
#define C_ 16
#define H_ 64
#define W_ 64
#define HW_ 4096

// fp16 images, layout [b][l][cq(2)][HW][8ch] : 16 B per (pixel, channel-oct)
__device__ __half g_imgh[(size_t)B_ * L_ * 2 * HW_ * 8];

// ---------------------------------------------------------------------------
// Kernel 1: repack [B][L][C][HW] fp32 -> [b][l][cq][HW][8] fp16.
// ---------------------------------------------------------------------------
__global__ __launch_bounds__(256) void transpose_kernel(const float* __restrict__ images) {
    int idx = blockIdx.x * blockDim.x + threadIdx.x;   // over B*L*2*HW
    int p = idx & (HW_ - 1);
    int cq = (idx >> 12) & 1;
    int bl = idx >> 13;
    const float* src = images + ((size_t)bl * C_ + cq * 8) * HW_ + p;
    __half2 h[4];
#pragma unroll
    for (int j = 0; j < 4; ++j)
        h[j] = __floats2half2_rn(src[(2 * j) * HW_], src[(2 * j + 1) * HW_]);
    ((uint4*)g_imgh)[idx] = *(uint4*)h;
}

// pack two copies of w into a 64-bit f32x2 operand
__device__ __forceinline__ unsigned long long packw(float w) {
    unsigned long long r;
    asm("mov.b64 %0, {%1, %1};" : "=l"(r) : "f"(w));
    return r;
}

// ---------------------------------------------------------------------------
// Accumulate 8 fp16 channels (one uint4) * packed weight into 4 f32x2 accs.
// fma.rn.f32x2: packed dual fp32 FMA (FFMA2) — identical arithmetic to two
// scalar fmaf, half the instructions.
// ---------------------------------------------------------------------------
__device__ __forceinline__ void accum8(unsigned long long* acc2, uint4 a,
                                       unsigned long long w2) {
    unsigned wds[4] = {a.x, a.y, a.z, a.w};
#pragma unroll
    for (int j = 0; j < 4; ++j) {
        float2 f = __half22float2(*(__half2*)&wds[j]);
        unsigned long long fv;
        asm("mov.b64 %0, {%1, %2};" : "=l"(fv) : "f"(f.x), "f"(f.y));
        asm("fma.rn.f32x2 %0, %1, %2, %3;"
            : "=l"(acc2[j]) : "l"(w2), "l"(fv), "l"(acc2[j]));
    }
}

// ---------------------------------------------------------------------------
// One bilinear sample of frame (imgu = cq0 plane ptr in uint4 units),
// accumulated into acc2[8] (= 16 fp32 channels) with rel flow (relx, rely).
// ---------------------------------------------------------------------------
__device__ __forceinline__ void sample_frame(const uint4* __restrict__ imgu,
                                             float ax, float yf,
                                             float relx, float rely,
                                             unsigned long long* acc2) {
    // wrap x: u = (gx+1) mod 2, ix = u*32 - 0.5 in [-0.5, 63.5)
    float u0 = ax + relx;
    float u = u0 - 2.0f * floorf(0.5f * u0);
    float ixf = fmaf(u, 32.0f, -0.5f);
    float iyf = fmaf(rely, 32.0f, yf);

    float x0f = floorf(ixf), y0f = floorf(iyf);
    float wx1 = ixf - x0f, wy1 = iyf - y0f;
    float wx0 = 1.0f - wx1, wy0 = 1.0f - wy1;
    int x0 = (int)x0f, y0 = (int)y0f;

    // validity folded into weights (x wrapped => x0 in [-1,63])
    if (x0 < 0) wx0 = 0.0f;
    if (x0 > 62) wx1 = 0.0f;
    if ((unsigned)y0 > 63u) wy0 = 0.0f;
    if ((unsigned)(y0 + 1) > 63u) wy1 = 0.0f;

    unsigned long long w00 = packw(wx0 * wy0), w10 = packw(wx1 * wy0);
    unsigned long long w01 = packw(wx0 * wy1), w11 = packw(wx1 * wy1);

    int x0c = max(x0, 0), x1c = min(x0 + 1, 63);
    int y0c = min(max(y0, 0), 63), y1c = min(max(y0 + 1, 0), 63);
    int p00 = (y0c << 6) + x0c, p10 = (y0c << 6) + x1c;
    int p01 = (y1c << 6) + x0c, p11 = (y1c << 6) + x1c;

    const uint4* hi = imgu + HW_;
    // batch all 8 corner loads for MLP
    uint4 a00 = imgu[p00], a10 = imgu[p10], a01 = imgu[p01], a11 = imgu[p11];
    uint4 b00 = hi[p00],   b10 = hi[p10],   b01 = hi[p01],   b11 = hi[p11];

    accum8(acc2,     a00, w00); accum8(acc2,     a10, w10);
    accum8(acc2,     a01, w01); accum8(acc2,     a11, w11);
    accum8(acc2 + 4, b00, w00); accum8(acc2 + 4, b10, w10);
    accum8(acc2 + 4, b01, w01); accum8(acc2 + 4, b11, w11);
}

// ---------------------------------------------------------------------------
// Kernel 2: main gather. 1 lane = 1 pixel, all 16 channels.
// Block = 128 threads = 2 rows of one (b,t); grid (32, 24, 2), t descending.
// rel flow reconstructed in-loop (k descending); k=0 iteration peeled.
// ---------------------------------------------------------------------------
__global__ __launch_bounds__(128) void warp_kernel(const float* __restrict__ flows,
                                                   float* __restrict__ out) {
    int tid = threadIdx.x;
    int x = tid & 63;
    int y = (blockIdx.x << 1) + (tid >> 6);
    int t = (L_ - 1) - (int)blockIdx.y;
    int b = blockIdx.z;
    int p = (y << 6) + x;

    float ax = (float)(2 * x + 1) * (1.0f / 64.0f);  // (bx + 1), pre-wrap
    float yf = (float)y;                              // iy = rely*32 + y

    const float* fptr = flows + ((size_t)(b * L_ + t) * 2) * HW_ + p;
    const uint4* imgu = (const uint4*)g_imgh + (size_t)(b * L_ + t) * 2 * HW_;

    float relx = 0.0f, rely = 0.0f;
    unsigned long long acc2[8];
#pragma unroll
    for (int j = 0; j < 8; ++j) acc2[j] = 0ull;      // (0.0f, 0.0f)

    for (int k = t; k > 0; --k) {
        float fx = fptr[0];
        float fy = fptr[HW_];
        sample_frame(imgu, ax, yf, relx, rely, acc2);
        relx += fx;
        rely += fy;
        fptr -= 2 * HW_;
        imgu -= 2 * HW_;
    }
    // k = 0: no flow load, no rel update
    sample_frame(imgu, ax, yf, relx, rely, acc2);

    // out layout [B][L][C][H][W]; warp writes 128B coalesced per channel
    float* op = out + ((size_t)(b * L_ + t) * C_) * HW_ + p;
#pragma unroll
    for (int j = 0; j < 8; ++j) {
        float lo, hi;
        asm("mov.b64 {%0, %1}, %2;" : "=f"(lo), "=f"(hi) : "l"(acc2[j]));
        op[(2 * j) * HW_]     = lo;
        op[(2 * j + 1) * HW_] = hi;
    }
}

extern "C" void kernel_launch(void* const* d_in, const int* in_sizes, int n_in,
                              void* d_out, int out_size) {
    const float* flows = (const float*)d_in[0];
    const float* images = (const float*)d_in[1];
    float* out = (float*)d_out;

    transpose_kernel<<<(B_ * L_ * 2 * HW_) / 256, 256>>>(images);
    dim3 grid(32, L_, B_);
    warp_kernel<<<grid, 128>>>(flows, out);
}

// round 16
// speedup vs baseline: 1.3763x; 1.0626x over previous
#include <cuda_runtime.h>
#include <cuda_fp16.h>

#define B_ 2
#define L_ 24
#define C_ 16
#define H_ 64
#define W_ 64
#define HW_ 4096

// fp16 images, layout [b][l][cq(2)][HW][8ch] : 16 B per (pixel, channel-oct)
__device__ __half g_imgh[(size_t)B_ * L_ * 2 * HW_ * 8];

// ---------------------------------------------------------------------------
// Kernel 1: repack [B][L][C][HW] fp32 -> [b][l][cq][HW][8] fp16.
// ---------------------------------------------------------------------------
__global__ __launch_bounds__(256) void transpose_kernel(const float* __restrict__ images) {
    int idx = blockIdx.x * blockDim.x + threadIdx.x;   // over B*L*2*HW
    int p = idx & (HW_ - 1);
    int cq = (idx >> 12) & 1;
    int bl = idx >> 13;
    const float* src = images + ((size_t)bl * C_ + cq * 8) * HW_ + p;
    __half2 h[4];
#pragma unroll
    for (int j = 0; j < 4; ++j)
        h[j] = __floats2half2_rn(src[(2 * j) * HW_], src[(2 * j + 1) * HW_]);
    ((uint4*)g_imgh)[idx] = *(uint4*)h;
}

// pack two copies of w into a 64-bit f32x2 operand
__device__ __forceinline__ unsigned long long packw(float w) {
    unsigned long long r;
    asm("mov.b64 %0, {%1, %1};" : "=l"(r) : "f"(w));
    return r;
}

// ---------------------------------------------------------------------------
// Accumulate 8 fp16 channels (one uint4) * packed weight into 4 f32x2 accs
// via fma.rn.f32x2 (FFMA2) — identical arithmetic, half the FMA instrs.
// ---------------------------------------------------------------------------
__device__ __forceinline__ void accum8(unsigned long long* acc2, uint4 a,
                                       unsigned long long w2) {
    unsigned wds[4] = {a.x, a.y, a.z, a.w};
#pragma unroll
    for (int j = 0; j < 4; ++j) {
        float2 f = __half22float2(*(__half2*)&wds[j]);
        unsigned long long fv;
        asm("mov.b64 %0, {%1, %2};" : "=l"(fv) : "f"(f.x), "f"(f.y));
        asm("fma.rn.f32x2 %0, %1, %2, %3;"
            : "=l"(acc2[j]) : "l"(w2), "l"(fv), "l"(acc2[j]));
    }
}

struct Corners {
    int p00, p10, p01, p11;
    unsigned long long w00, w10, w01, w11;
};

__device__ __forceinline__ Corners make_corners(float ax, float yf,
                                                float relx, float rely) {
    Corners c;
    // wrap x: u = (gx+1) mod 2, ix = u*32 - 0.5 in [-0.5, 63.5)
    float u0 = ax + relx;
    float u = u0 - 2.0f * floorf(0.5f * u0);
    float ixf = fmaf(u, 32.0f, -0.5f);
    float iyf = fmaf(rely, 32.0f, yf);

    float x0f = floorf(ixf), y0f = floorf(iyf);
    float wx1 = ixf - x0f, wy1 = iyf - y0f;
    float wx0 = 1.0f - wx1, wy0 = 1.0f - wy1;
    int x0 = (int)x0f, y0 = (int)y0f;

    if (x0 < 0) wx0 = 0.0f;
    if (x0 > 62) wx1 = 0.0f;
    if ((unsigned)y0 > 63u) wy0 = 0.0f;
    if ((unsigned)(y0 + 1) > 63u) wy1 = 0.0f;

    c.w00 = packw(wx0 * wy0); c.w10 = packw(wx1 * wy0);
    c.w01 = packw(wx0 * wy1); c.w11 = packw(wx1 * wy1);

    int x0c = max(x0, 0), x1c = min(x0 + 1, 63);
    int y0c = min(max(y0, 0), 63), y1c = min(max(y0 + 1, 0), 63);
    c.p00 = (y0c << 6) + x0c; c.p10 = (y0c << 6) + x1c;
    c.p01 = (y1c << 6) + x0c; c.p11 = (y1c << 6) + x1c;
    return c;
}

// Single-frame sample (used for the leftover frame 0 when t is even).
__device__ __forceinline__ void sample_frame(const uint4* __restrict__ imgu,
                                             float ax, float yf,
                                             float relx, float rely,
                                             unsigned long long* acc2) {
    Corners c = make_corners(ax, yf, relx, rely);
    const uint4* hi = imgu + HW_;
    uint4 a00 = imgu[c.p00], a10 = imgu[c.p10], a01 = imgu[c.p01], a11 = imgu[c.p11];
    uint4 b00 = hi[c.p00],   b10 = hi[c.p10],   b01 = hi[c.p01],   b11 = hi[c.p11];
    accum8(acc2,     a00, c.w00); accum8(acc2,     a10, c.w10);
    accum8(acc2,     a01, c.w01); accum8(acc2,     a11, c.w11);
    accum8(acc2 + 4, b00, c.w00); accum8(acc2 + 4, b10, c.w10);
    accum8(acc2 + 4, b01, c.w01); accum8(acc2 + 4, b11, c.w11);
}

// ---------------------------------------------------------------------------
// Kernel 2: main gather, k-pairwise pipelined.
// Block = 128 threads = 2 rows of one (b,t); grid (32, 24, 2), t descending.
// Each iteration handles frames (k, k-1); the two frames' corner loads are
// interleaved so independent gathers from both frames are in flight together.
// ---------------------------------------------------------------------------
__global__ __launch_bounds__(128) void warp_kernel(const float* __restrict__ flows,
                                                   float* __restrict__ out) {
    int tid = threadIdx.x;
    int x = tid & 63;
    int y = (blockIdx.x << 1) + (tid >> 6);
    int t = (L_ - 1) - (int)blockIdx.y;
    int b = blockIdx.z;
    int p = (y << 6) + x;

    float ax = (float)(2 * x + 1) * (1.0f / 64.0f);  // (bx + 1), pre-wrap
    float yf = (float)y;                              // iy = rely*32 + y

    const float* fbase = flows + ((size_t)(b * L_)) * 2 * HW_ + p;
    const uint4* img0 = (const uint4*)g_imgh + (size_t)(b * L_) * 2 * HW_;

    float relx = 0.0f, rely = 0.0f;
    unsigned long long acc2[8];
#pragma unroll
    for (int j = 0; j < 8; ++j) acc2[j] = 0ull;      // (0.0f, 0.0f)

    int k = t;
    while (k >= 1) {
        // flows for this pair (f_k always needed; f_{k-1} only if k-1 >= 1)
        float fkx = fbase[(size_t)k * 2 * HW_];
        float fky = fbase[(size_t)k * 2 * HW_ + HW_];
        float f2x = 0.0f, f2y = 0.0f;
        if (k >= 2) {
            f2x = fbase[(size_t)(k - 1) * 2 * HW_];
            f2y = fbase[(size_t)(k - 1) * 2 * HW_ + HW_];
        }

        Corners cA = make_corners(ax, yf, relx, rely);          // frame k
        float rBx = relx + fkx, rBy = rely + fky;
        Corners cB = make_corners(ax, yf, rBx, rBy);            // frame k-1

        const uint4* loA = img0 + (size_t)k * 2 * HW_;
        const uint4* hiA = loA + HW_;
        const uint4* loB = img0 + (size_t)(k - 1) * 2 * HW_;
        const uint4* hiB = loB + HW_;

        // interleaved load/accum: keep <= 8 uint4 live, two frames in flight
        uint4 a0 = loA[cA.p00], a1 = loA[cA.p10], a2 = loA[cA.p01], a3 = loA[cA.p11];
        uint4 c0 = loB[cB.p00], c1 = loB[cB.p10], c2 = loB[cB.p01], c3 = loB[cB.p11];
        accum8(acc2, a0, cA.w00); accum8(acc2, a1, cA.w10);
        accum8(acc2, a2, cA.w01); accum8(acc2, a3, cA.w11);
        uint4 b0 = hiA[cA.p00], b1 = hiA[cA.p10], b2 = hiA[cA.p01], b3 = hiA[cA.p11];
        accum8(acc2, c0, cB.w00); accum8(acc2, c1, cB.w10);
        accum8(acc2, c2, cB.w01); accum8(acc2, c3, cB.w11);
        uint4 d0 = hiB[cB.p00], d1 = hiB[cB.p10], d2 = hiB[cB.p01], d3 = hiB[cB.p11];
        accum8(acc2 + 4, b0, cA.w00); accum8(acc2 + 4, b1, cA.w10);
        accum8(acc2 + 4, b2, cA.w01); accum8(acc2 + 4, b3, cA.w11);
        accum8(acc2 + 4, d0, cB.w00); accum8(acc2 + 4, d1, cB.w10);
        accum8(acc2 + 4, d2, cB.w01); accum8(acc2 + 4, d3, cB.w11);

        relx = rBx + f2x;
        rely = rBy + f2y;
        k -= 2;
    }
    if (k == 0)   // t even: leftover frame 0
        sample_frame(img0, ax, yf, relx, rely, acc2);

    // out layout [B][L][C][H][W]; warp writes 128B coalesced per channel
    float* op = out + ((size_t)(b * L_ + t) * C_) * HW_ + p;
#pragma unroll
    for (int j = 0; j < 8; ++j) {
        float lo, hi;
        asm("mov.b64 {%0, %1}, %2;" : "=f"(lo), "=f"(hi) : "l"(acc2[j]));
        op[(2 * j) * HW_]     = lo;
        op[(2 * j + 1) * HW_] = hi;
    }
}

extern "C" void kernel_launch(void* const* d_in, const int* in_sizes, int n_in,
                              void* d_out, int out_size) {
    const float* flows = (const float*)d_in[0];
    const float* images = (const float*)d_in[1];
    float* out = (float*)d_out;

    transpose_kernel<<<(B_ * L_ * 2 * HW_) / 256, 256>>>(images);
    dim3 grid(32, L_, B_);
    warp_kernel<<<grid, 128>>>(flows, out);
}